// round 5
// baseline (speedup 1.0000x reference)
#include <cuda_runtime.h>
#include <cuda_bf16.h>
#include <cstdint>

#define BATCH 64
#define NQ 197
#define DIM 768
#define NH 12
#define HD 64
#define NUM_REL 732
#define MROWS (BATCH * NQ)   // 12608

#define XN (MROWS * DIM)         // 9,682,944
#define QKN (BATCH * NH * NQ * HD)  // 9,682,944
#define W1N (3 * DIM * DIM)      // 1,769,472
#define W2N (DIM * DIM)          // 589,824

static __device__ __nv_bfloat16 g_Xh[XN],  g_Xl[XN];
static __device__ __nv_bfloat16 g_W1h[W1N], g_W1l[W1N];
static __device__ __nv_bfloat16 g_W2h[W2N], g_W2l[W2N];
static __device__ __nv_bfloat16 g_Qh[QKN], g_Ql[QKN];
static __device__ __nv_bfloat16 g_Kh[QKN], g_Kl[QKN];
static __device__ __nv_bfloat16 g_Vh[QKN], g_Vl[QKN];
static __device__ __nv_bfloat16 g_AOh[XN], g_AOl[XN];

// ---------------------------------------------------------------------------
// helpers
// ---------------------------------------------------------------------------
__device__ __forceinline__ uint32_t smem_u32(const void* p) {
    uint32_t a;
    asm("{ .reg .u64 t; cvta.to.shared.u64 t, %1; cvt.u32.u64 %0, t; }" : "=r"(a) : "l"(p));
    return a;
}

__device__ __forceinline__ void ldsm4(uint32_t* r, uint32_t addr) {
    asm volatile("ldmatrix.sync.aligned.m8n8.x4.shared.b16 {%0,%1,%2,%3}, [%4];"
                 : "=r"(r[0]), "=r"(r[1]), "=r"(r[2]), "=r"(r[3]) : "r"(addr));
}

__device__ __forceinline__ void ldsm4t(uint32_t* r, uint32_t addr) {
    asm volatile("ldmatrix.sync.aligned.m8n8.x4.trans.shared.b16 {%0,%1,%2,%3}, [%4];"
                 : "=r"(r[0]), "=r"(r[1]), "=r"(r[2]), "=r"(r[3]) : "r"(addr));
}

__device__ __forceinline__ void mma16816(float* c, const uint32_t* a, const uint32_t* b) {
    asm volatile(
        "mma.sync.aligned.m16n8k16.row.col.f32.bf16.bf16.f32 "
        "{%0,%1,%2,%3}, {%4,%5,%6,%7}, {%8,%9}, {%0,%1,%2,%3};"
        : "+f"(c[0]), "+f"(c[1]), "+f"(c[2]), "+f"(c[3])
        : "r"(a[0]), "r"(a[1]), "r"(a[2]), "r"(a[3]), "r"(b[0]), "r"(b[1]));
}

__device__ __forceinline__ void split2(float x, float y, uint32_t& hi, uint32_t& lo) {
    __nv_bfloat162 h = __floats2bfloat162_rn(x, y);
    float hx = __bfloat162float(h.x);
    float hy = __bfloat162float(h.y);
    __nv_bfloat162 l = __floats2bfloat162_rn(x - hx, y - hy);
    hi = *reinterpret_cast<uint32_t*>(&h);
    lo = *reinterpret_cast<uint32_t*>(&l);
}

__device__ __forceinline__ void cp16(uint32_t dst, const void* src, uint32_t srcbytes) {
    asm volatile("cp.async.cg.shared.global [%0], [%1], 16, %2;"
                 :: "r"(dst), "l"(src), "r"(srcbytes) : "memory");
}
#define CP_COMMIT() asm volatile("cp.async.commit_group;" ::: "memory")
#define CP_WAIT(N)  asm volatile("cp.async.wait_group %0;" :: "n"(N) : "memory")

// ---------------------------------------------------------------------------
// split kernel: fp32 -> bf16 hi/lo
// ---------------------------------------------------------------------------
__global__ void split_kernel(const float* __restrict__ in, __nv_bfloat16* __restrict__ hi,
                             __nv_bfloat16* __restrict__ lo, int n4) {
    int i = blockIdx.x * 256 + threadIdx.x;
    if (i < n4) {
        float4 v = reinterpret_cast<const float4*>(in)[i];
        uint32_t h0, l0, h1, l1;
        split2(v.x, v.y, h0, l0);
        split2(v.z, v.w, h1, l1);
        reinterpret_cast<uint2*>(hi)[i] = make_uint2(h0, h1);
        reinterpret_cast<uint2*>(lo)[i] = make_uint2(l0, l1);
    }
}

// ---------------------------------------------------------------------------
// bf16x3 GEMM, pre-split bf16 inputs, cp.async 4-stage pipeline.
// C[m][n] = sum_k A[m][k]*B[n][k], K=768. CTA tile 128x128, BK=32, 8 warps.
// smem row stride: 40 bf16 (80 B).
// ---------------------------------------------------------------------------
#define TILE2 (128 * 80)            // 10240 B per matrix per split per stage
#define STG2  (4 * TILE2)           // 40960 B per stage
#define NSTAGE 4
#define GS2_TOTAL (NSTAGE * STG2)   // 163840 B
#define NKT (DIM / 32)              // 24

template <typename Epi>
__global__ __launch_bounds__(256, 1)
void mgemm2(const __nv_bfloat16* __restrict__ Ah, const __nv_bfloat16* __restrict__ Al,
            const __nv_bfloat16* __restrict__ Bh, const __nv_bfloat16* __restrict__ Bl,
            int M, Epi epi) {
    extern __shared__ char smem[];
    const uint32_t sb = smem_u32(smem);
    const int tid = threadIdx.x;
    const int warp = tid >> 5;
    const int lane = tid & 31;
    const int wm = warp >> 2;
    const int wn = warp & 3;
    const int m0 = blockIdx.y * 128;
    const int n0 = blockIdx.x * 128;

    float acc[4][4][4];
#pragma unroll
    for (int i = 0; i < 4; i++)
#pragma unroll
        for (int j = 0; j < 4; j++)
#pragma unroll
            for (int k = 0; k < 4; k++) acc[i][j][k] = 0.f;

    uint32_t aoff[4], boff[2];
#pragma unroll
    for (int mf = 0; mf < 4; mf++)
        aoff[mf] = (uint32_t)((wm * 64 + mf * 16 + (lane & 15)) * 80 + (lane >> 4) * 16);
#pragma unroll
    for (int pr = 0; pr < 2; pr++)
        boff[pr] = (uint32_t)(2 * TILE2 +
                   (wn * 32 + pr * 16 + ((lane >> 4) * 8) + (lane & 7)) * 80 +
                   ((lane >> 3) & 1) * 16);

    // per-thread load chunks: ids tid and tid+256 (512 chunks of 16B per matrix)
    const int r0c = tid >> 2, c40 = tid & 3;
    const int r1c = (tid + 256) >> 2, c41 = (tid + 256) & 3;

    auto load_stage = [&](int kt) {
        const uint32_t sbase = sb + (uint32_t)((kt & (NSTAGE - 1)) * STG2);
#pragma unroll
        for (int i = 0; i < 2; i++) {
            int row = i ? r1c : r0c;
            int c4 = i ? c41 : c40;
            uint32_t doff = (uint32_t)(row * 80 + c4 * 16);
            int m = m0 + row;
            int mc = (m < M) ? m : 0;
            uint32_t sz = (m < M) ? 16u : 0u;
            size_t ga = (size_t)mc * DIM + kt * 32 + c4 * 8;
            cp16(sbase + doff,         Ah + ga, sz);
            cp16(sbase + TILE2 + doff, Al + ga, sz);
            size_t gb = (size_t)(n0 + row) * DIM + kt * 32 + c4 * 8;
            cp16(sbase + 2 * TILE2 + doff, Bh + gb, 16u);
            cp16(sbase + 3 * TILE2 + doff, Bl + gb, 16u);
        }
        CP_COMMIT();
    };

    auto compute = [&](int st) {
        const uint32_t sadd = sb + (uint32_t)(st * STG2);
#pragma unroll
        for (int ks = 0; ks < 2; ks++) {
            uint32_t ah[4][4], al[4][4];
#pragma unroll
            for (int mf = 0; mf < 4; mf++) {
                ldsm4(ah[mf], sadd + aoff[mf] + ks * 32);
                ldsm4(al[mf], sadd + TILE2 + aoff[mf] + ks * 32);
            }
            uint32_t bh[4][2], bl[4][2];
#pragma unroll
            for (int pr = 0; pr < 2; pr++) {
                uint32_t t[4];
                ldsm4(t, sadd + boff[pr] + ks * 32);
                bh[2 * pr][0] = t[0]; bh[2 * pr][1] = t[1];
                bh[2 * pr + 1][0] = t[2]; bh[2 * pr + 1][1] = t[3];
                ldsm4(t, sadd + TILE2 + boff[pr] + ks * 32);
                bl[2 * pr][0] = t[0]; bl[2 * pr][1] = t[1];
                bl[2 * pr + 1][0] = t[2]; bl[2 * pr + 1][1] = t[3];
            }
#pragma unroll
            for (int mf = 0; mf < 4; mf++)
#pragma unroll
                for (int nf = 0; nf < 4; nf++) {
                    mma16816(acc[mf][nf], ah[mf], bh[nf]);
                    mma16816(acc[mf][nf], ah[mf], bl[nf]);
                    mma16816(acc[mf][nf], al[mf], bh[nf]);
                }
        }
    };

    load_stage(0);
    load_stage(1);
    load_stage(2);

    for (int kt = 0; kt < NKT; kt++) {
        CP_WAIT(2);
        __syncthreads();
        if (kt + 3 < NKT) load_stage(kt + 3);
        compute(kt & (NSTAGE - 1));
    }

    const int g = lane >> 2;
    const int tig = lane & 3;
#pragma unroll
    for (int mf = 0; mf < 4; mf++) {
#pragma unroll
        for (int nf = 0; nf < 4; nf++) {
            int m = m0 + wm * 64 + mf * 16 + g;
            int n = n0 + wn * 32 + nf * 8 + tig * 2;
            if (m < M)     epi(m, n, make_float2(acc[mf][nf][0], acc[mf][nf][1]));
            if (m + 8 < M) epi(m + 8, n, make_float2(acc[mf][nf][2], acc[mf][nf][3]));
        }
    }
}

struct QKVEpiS {
    const float* qb;
    const float* vb;
    __nv_bfloat16 *Qh, *Ql, *Kh, *Kl, *Vh, *Vl;
    __device__ __forceinline__ void operator()(int m, int n, float2 v) const {
        int part = n / DIM;
        int c = n - part * DIM;
        int h = c >> 6;
        int d = c & 63;
        int b = m / NQ;
        int r = m - b * NQ;
        size_t idx = ((size_t)((b * NH + h) * NQ + r)) * HD + d;
        uint32_t hi, lo;
        if (part == 0) {
            v.x = (v.x + qb[c]) * 0.125f;
            v.y = (v.y + qb[c + 1]) * 0.125f;
            split2(v.x, v.y, hi, lo);
            *reinterpret_cast<uint32_t*>(Qh + idx) = hi;
            *reinterpret_cast<uint32_t*>(Ql + idx) = lo;
        } else if (part == 1) {
            split2(v.x, v.y, hi, lo);
            *reinterpret_cast<uint32_t*>(Kh + idx) = hi;
            *reinterpret_cast<uint32_t*>(Kl + idx) = lo;
        } else {
            v.x += vb[c];
            v.y += vb[c + 1];
            split2(v.x, v.y, hi, lo);
            *reinterpret_cast<uint32_t*>(Vh + idx) = hi;
            *reinterpret_cast<uint32_t*>(Vl + idx) = lo;
        }
    }
};

struct ProjEpi2 {
    const float* pb;
    float* out;
    __device__ __forceinline__ void operator()(int m, int n, float2 v) const {
        v.x += pb[n];
        v.y += pb[n + 1];
        *reinterpret_cast<float2*>(out + (size_t)m * DIM + n) = v;
    }
};

// ---------------------------------------------------------------------------
// Tensor-core attention on pre-split bf16 Q/K/V; epilogue writes AO hi/lo.
// ---------------------------------------------------------------------------
#define NQP 208
#define KSTR_B 144
#define AMAT_B (NQP * KSTR_B)
#define ASMEM_TOTAL (6 * AMAT_B + NUM_REL * 4)

__global__ __launch_bounds__(256, 1)
void attn_mma(const __nv_bfloat16* __restrict__ Qh, const __nv_bfloat16* __restrict__ Ql,
              const __nv_bfloat16* __restrict__ Kh, const __nv_bfloat16* __restrict__ Kl,
              const __nv_bfloat16* __restrict__ Vh, const __nv_bfloat16* __restrict__ Vl,
              const float* __restrict__ tabg, const int* __restrict__ ridx,
              __nv_bfloat16* __restrict__ AOh, __nv_bfloat16* __restrict__ AOl) {
    extern __shared__ char sm[];
    const uint32_t sb = smem_u32(sm);
    const uint32_t sQh = sb;
    const uint32_t sQl = sb + AMAT_B;
    const uint32_t sKh = sb + 2 * AMAT_B;
    const uint32_t sKl = sb + 3 * AMAT_B;
    const uint32_t sVh = sb + 4 * AMAT_B;
    const uint32_t sVl = sb + 5 * AMAT_B;
    float* tab = reinterpret_cast<float*>(sm + 6 * AMAT_B);

    const int bh = blockIdx.x;
    const int h = bh % NH;
    const int b = bh / NH;
    const int tid = threadIdx.x;
    const int warp = tid >> 5;
    const int lane = tid & 31;
    const int g = lane >> 2;
    const int tig = lane & 3;
    const size_t base = (size_t)bh * NQ * HD;

    // zero pad rows 197..207 in all six arrays
    for (int i = tid; i < 11 * 9; i += 256) {
        int r = 197 + i / 9;
        int c = i % 9;
        uint32_t off = (uint32_t)(r * KSTR_B + c * 16);
#pragma unroll
        for (int a = 0; a < 6; a++)
            *reinterpret_cast<uint4*>(sm + a * AMAT_B + off) = make_uint4(0u, 0u, 0u, 0u);
    }
    // cp.async stage: 197 rows x 8 chunks of 16B per array
    for (int c = tid; c < NQ * 8; c += 256) {
        int r = c >> 3;
        int col = c & 7;
        uint32_t doff = (uint32_t)(r * KSTR_B + col * 16);
        size_t ga = base + (size_t)r * HD + col * 8;
        cp16(sQh + doff, Qh + ga, 16u);
        cp16(sQl + doff, Ql + ga, 16u);
        cp16(sKh + doff, Kh + ga, 16u);
        cp16(sKl + doff, Kl + ga, 16u);
        cp16(sVh + doff, Vh + ga, 16u);
        cp16(sVl + doff, Vl + ga, 16u);
    }
    CP_COMMIT();
    for (int i = tid; i < NUM_REL; i += 256) tab[i] = tabg[i * NH + h];
    CP_WAIT(0);
    __syncthreads();

    for (int blk = warp; blk < 13; blk += 8) {
        float s[26][4];
#pragma unroll
        for (int nc = 0; nc < 26; nc++)
#pragma unroll
            for (int e = 0; e < 4; e++) s[nc][e] = 0.f;

        const uint32_t qrow = (uint32_t)((blk * 16 + (lane & 15)) * KSTR_B + (lane >> 4) * 16);
        const uint32_t krow = (uint32_t)(((lane >> 4) * 8 + (lane & 7)) * KSTR_B + ((lane >> 3) & 1) * 16);

#pragma unroll
        for (int kc = 0; kc < 4; kc++) {
            uint32_t qh[4], ql[4];
            ldsm4(qh, sQh + qrow + kc * 32);
            ldsm4(ql, sQl + qrow + kc * 32);
#pragma unroll
            for (int np = 0; np < 13; np++) {
                uint32_t th[4], tl[4];
                ldsm4(th, sKh + krow + (uint32_t)(np * 16 * KSTR_B) + kc * 32);
                ldsm4(tl, sKl + krow + (uint32_t)(np * 16 * KSTR_B) + kc * 32);
                mma16816(s[2 * np],     qh, th);
                mma16816(s[2 * np],     qh, tl);
                mma16816(s[2 * np],     ql, th);
                mma16816(s[2 * np + 1], qh, th + 2);
                mma16816(s[2 * np + 1], qh, tl + 2);
                mma16816(s[2 * np + 1], ql, th + 2);
            }
        }

        const int q0 = blk * 16 + g;
        const int q1 = q0 + 8;
        const int* r0 = ridx + (size_t)min(q0, NQ - 1) * NQ;
        const int* r1 = ridx + (size_t)min(q1, NQ - 1) * NQ;
#pragma unroll
        for (int nc = 0; nc < 26; nc++) {
            int n0 = nc * 8 + tig * 2;
            if (n0 < NQ) { s[nc][0] += tab[r0[n0]]; s[nc][2] += tab[r1[n0]]; }
            else         { s[nc][0] = -1e30f;       s[nc][2] = -1e30f; }
            int n1 = n0 + 1;
            if (n1 < NQ) { s[nc][1] += tab[r0[n1]]; s[nc][3] += tab[r1[n1]]; }
            else         { s[nc][1] = -1e30f;       s[nc][3] = -1e30f; }
        }

        float mx0 = -1e30f, mx1 = -1e30f;
#pragma unroll
        for (int nc = 0; nc < 26; nc++) {
            mx0 = fmaxf(mx0, fmaxf(s[nc][0], s[nc][1]));
            mx1 = fmaxf(mx1, fmaxf(s[nc][2], s[nc][3]));
        }
        mx0 = fmaxf(mx0, __shfl_xor_sync(0xffffffffu, mx0, 1));
        mx0 = fmaxf(mx0, __shfl_xor_sync(0xffffffffu, mx0, 2));
        mx1 = fmaxf(mx1, __shfl_xor_sync(0xffffffffu, mx1, 1));
        mx1 = fmaxf(mx1, __shfl_xor_sync(0xffffffffu, mx1, 2));

        float sum0 = 0.f, sum1 = 0.f;
#pragma unroll
        for (int nc = 0; nc < 26; nc++) {
            s[nc][0] = __expf(s[nc][0] - mx0);
            s[nc][1] = __expf(s[nc][1] - mx0);
            s[nc][2] = __expf(s[nc][2] - mx1);
            s[nc][3] = __expf(s[nc][3] - mx1);
            sum0 += s[nc][0] + s[nc][1];
            sum1 += s[nc][2] + s[nc][3];
        }
        sum0 += __shfl_xor_sync(0xffffffffu, sum0, 1);
        sum0 += __shfl_xor_sync(0xffffffffu, sum0, 2);
        sum1 += __shfl_xor_sync(0xffffffffu, sum1, 1);
        sum1 += __shfl_xor_sync(0xffffffffu, sum1, 2);
        float inv0 = __frcp_rn(sum0);
        float inv1 = __frcp_rn(sum1);
#pragma unroll
        for (int nc = 0; nc < 26; nc++) {
            s[nc][0] *= inv0; s[nc][1] *= inv0;
            s[nc][2] *= inv1; s[nc][3] *= inv1;
        }

        float o[8][4];
#pragma unroll
        for (int nd = 0; nd < 8; nd++)
#pragma unroll
            for (int e = 0; e < 4; e++) o[nd][e] = 0.f;

        const uint32_t vrow = (uint32_t)((((lane >> 3) & 1) * 8 + (lane & 7)) * KSTR_B + (lane >> 4) * 16);

#pragma unroll
        for (int kc = 0; kc < 13; kc++) {
            uint32_t ph[4], pl[4];
            split2(s[2 * kc][0],     s[2 * kc][1],     ph[0], pl[0]);
            split2(s[2 * kc][2],     s[2 * kc][3],     ph[1], pl[1]);
            split2(s[2 * kc + 1][0], s[2 * kc + 1][1], ph[2], pl[2]);
            split2(s[2 * kc + 1][2], s[2 * kc + 1][3], ph[3], pl[3]);
#pragma unroll
            for (int dg = 0; dg < 4; dg++) {
                uint32_t bh4[4], bl4[4];
                ldsm4t(bh4, sVh + vrow + (uint32_t)(kc * 16 * KSTR_B) + dg * 32);
                ldsm4t(bl4, sVl + vrow + (uint32_t)(kc * 16 * KSTR_B) + dg * 32);
                mma16816(o[2 * dg],     ph, bh4);
                mma16816(o[2 * dg],     ph, bl4);
                mma16816(o[2 * dg],     pl, bh4);
                mma16816(o[2 * dg + 1], ph, bh4 + 2);
                mma16816(o[2 * dg + 1], ph, bl4 + 2);
                mma16816(o[2 * dg + 1], pl, bh4 + 2);
            }
        }

        if (q0 < NQ) {
            size_t ob = ((size_t)(b * NQ + q0) * NH + h) * HD + tig * 2;
#pragma unroll
            for (int nd = 0; nd < 8; nd++) {
                uint32_t hi, lo;
                split2(o[nd][0], o[nd][1], hi, lo);
                *reinterpret_cast<uint32_t*>(AOh + ob + nd * 8) = hi;
                *reinterpret_cast<uint32_t*>(AOl + ob + nd * 8) = lo;
            }
        }
        if (q1 < NQ) {
            size_t ob = ((size_t)(b * NQ + q1) * NH + h) * HD + tig * 2;
#pragma unroll
            for (int nd = 0; nd < 8; nd++) {
                uint32_t hi, lo;
                split2(o[nd][2], o[nd][3], hi, lo);
                *reinterpret_cast<uint32_t*>(AOh + ob + nd * 8) = hi;
                *reinterpret_cast<uint32_t*>(AOl + ob + nd * 8) = lo;
            }
        }
    }
}

// ---------------------------------------------------------------------------
extern "C" void kernel_launch(void* const* d_in, const int* in_sizes, int n_in,
                              void* d_out, int out_size) {
    const float* x      = (const float*)d_in[0];
    const float* qkv_w  = (const float*)d_in[1];
    const float* q_bias = (const float*)d_in[2];
    const float* v_bias = (const float*)d_in[3];
    const float* rpb    = (const float*)d_in[4];
    const float* proj_w = (const float*)d_in[5];
    const float* proj_b = (const float*)d_in[6];
    const int*   ridx   = (const int*)d_in[7];
    float* out = (float*)d_out;

    __nv_bfloat16 *Xh, *Xl, *W1h, *W1l, *W2h, *W2l;
    __nv_bfloat16 *Qh, *Ql, *Kh, *Kl, *Vh, *Vl, *AOh, *AOl;
    cudaGetSymbolAddress((void**)&Xh, g_Xh);   cudaGetSymbolAddress((void**)&Xl, g_Xl);
    cudaGetSymbolAddress((void**)&W1h, g_W1h); cudaGetSymbolAddress((void**)&W1l, g_W1l);
    cudaGetSymbolAddress((void**)&W2h, g_W2h); cudaGetSymbolAddress((void**)&W2l, g_W2l);
    cudaGetSymbolAddress((void**)&Qh, g_Qh);   cudaGetSymbolAddress((void**)&Ql, g_Ql);
    cudaGetSymbolAddress((void**)&Kh, g_Kh);   cudaGetSymbolAddress((void**)&Kl, g_Kl);
    cudaGetSymbolAddress((void**)&Vh, g_Vh);   cudaGetSymbolAddress((void**)&Vl, g_Vl);
    cudaGetSymbolAddress((void**)&AOh, g_AOh); cudaGetSymbolAddress((void**)&AOl, g_AOl);

    cudaFuncSetAttribute(mgemm2<QKVEpiS>, cudaFuncAttributeMaxDynamicSharedMemorySize, GS2_TOTAL);
    cudaFuncSetAttribute(mgemm2<ProjEpi2>, cudaFuncAttributeMaxDynamicSharedMemorySize, GS2_TOTAL);
    cudaFuncSetAttribute(attn_mma, cudaFuncAttributeMaxDynamicSharedMemorySize, ASMEM_TOTAL);

    // 0) precompute bf16 hi/lo splits
    split_kernel<<<(XN / 4 + 255) / 256, 256>>>(x, Xh, Xl, XN / 4);
    split_kernel<<<(W1N / 4 + 255) / 256, 256>>>(qkv_w, W1h, W1l, W1N / 4);
    split_kernel<<<(W2N / 4 + 255) / 256, 256>>>(proj_w, W2h, W2l, W2N / 4);

    // 1) fused QKV projection -> pre-split Q (scaled), K, V
    QKVEpiS e1{q_bias, v_bias, Qh, Ql, Kh, Kl, Vh, Vl};
    mgemm2<QKVEpiS><<<dim3(3 * DIM / 128, (MROWS + 127) / 128), 256, GS2_TOTAL>>>(
        Xh, Xl, W1h, W1l, MROWS, e1);

    // 2) tensor-core attention with relative position bias
    attn_mma<<<BATCH * NH, 256, ASMEM_TOTAL>>>(Qh, Ql, Kh, Kl, Vh, Vl, rpb, ridx, AOh, AOl);

    // 3) output projection
    ProjEpi2 e2{proj_b, out};
    mgemm2<ProjEpi2><<<dim3(DIM / 128, (MROWS + 127) / 128), 256, GS2_TOTAL>>>(
        AOh, AOl, W2h, W2l, MROWS, e2);
}

// round 6
// speedup vs baseline: 1.1425x; 1.1425x over previous
#include <cuda_runtime.h>
#include <cuda_bf16.h>
#include <cstdint>

#define BATCH 64
#define NQ 197
#define DIM 768
#define NH 12
#define HD 64
#define NUM_REL 732
#define MROWS (BATCH * NQ)   // 12608

#define XN (MROWS * DIM)
#define QKN (BATCH * NH * NQ * HD)
#define W1N (3 * DIM * DIM)
#define W2N (DIM * DIM)

static __device__ __nv_bfloat16 g_Xh[XN],  g_Xl[XN];
static __device__ __nv_bfloat16 g_W1h[W1N], g_W1l[W1N];
static __device__ __nv_bfloat16 g_W2h[W2N], g_W2l[W2N];
static __device__ __nv_bfloat16 g_Qh[QKN], g_Ql[QKN];
static __device__ __nv_bfloat16 g_Kh[QKN], g_Kl[QKN];
static __device__ __nv_bfloat16 g_Vh[QKN], g_Vl[QKN];
static __device__ __nv_bfloat16 g_AOh[XN], g_AOl[XN];

// ---------------------------------------------------------------------------
// helpers
// ---------------------------------------------------------------------------
__device__ __forceinline__ uint32_t smem_u32(const void* p) {
    uint32_t a;
    asm("{ .reg .u64 t; cvta.to.shared.u64 t, %1; cvt.u32.u64 %0, t; }" : "=r"(a) : "l"(p));
    return a;
}

__device__ __forceinline__ void ldsm4(uint32_t* r, uint32_t addr) {
    asm volatile("ldmatrix.sync.aligned.m8n8.x4.shared.b16 {%0,%1,%2,%3}, [%4];"
                 : "=r"(r[0]), "=r"(r[1]), "=r"(r[2]), "=r"(r[3]) : "r"(addr));
}

__device__ __forceinline__ void ldsm4t(uint32_t* r, uint32_t addr) {
    asm volatile("ldmatrix.sync.aligned.m8n8.x4.trans.shared.b16 {%0,%1,%2,%3}, [%4];"
                 : "=r"(r[0]), "=r"(r[1]), "=r"(r[2]), "=r"(r[3]) : "r"(addr));
}

__device__ __forceinline__ void mma16816(float* c, const uint32_t* a, const uint32_t* b) {
    asm volatile(
        "mma.sync.aligned.m16n8k16.row.col.f32.bf16.bf16.f32 "
        "{%0,%1,%2,%3}, {%4,%5,%6,%7}, {%8,%9}, {%0,%1,%2,%3};"
        : "+f"(c[0]), "+f"(c[1]), "+f"(c[2]), "+f"(c[3])
        : "r"(a[0]), "r"(a[1]), "r"(a[2]), "r"(a[3]), "r"(b[0]), "r"(b[1]));
}

__device__ __forceinline__ void split2(float x, float y, uint32_t& hi, uint32_t& lo) {
    __nv_bfloat162 h = __floats2bfloat162_rn(x, y);
    float hx = __bfloat162float(h.x);
    float hy = __bfloat162float(h.y);
    __nv_bfloat162 l = __floats2bfloat162_rn(x - hx, y - hy);
    hi = *reinterpret_cast<uint32_t*>(&h);
    lo = *reinterpret_cast<uint32_t*>(&l);
}

__device__ __forceinline__ void cp16(uint32_t dst, const void* src, uint32_t srcbytes) {
    asm volatile("cp.async.cg.shared.global [%0], [%1], 16, %2;"
                 :: "r"(dst), "l"(src), "r"(srcbytes) : "memory");
}
#define CP_COMMIT() asm volatile("cp.async.commit_group;" ::: "memory")
#define CP_WAIT(N)  asm volatile("cp.async.wait_group %0;" :: "n"(N) : "memory")

// ---------------------------------------------------------------------------
// split kernel: fp32 -> bf16 hi/lo
// ---------------------------------------------------------------------------
__global__ void split_kernel(const float* __restrict__ in, __nv_bfloat16* __restrict__ hi,
                             __nv_bfloat16* __restrict__ lo, int n4) {
    int i = blockIdx.x * 256 + threadIdx.x;
    if (i < n4) {
        float4 v = reinterpret_cast<const float4*>(in)[i];
        uint32_t h0, l0, h1, l1;
        split2(v.x, v.y, h0, l0);
        split2(v.z, v.w, h1, l1);
        reinterpret_cast<uint2*>(hi)[i] = make_uint2(h0, h1);
        reinterpret_cast<uint2*>(lo)[i] = make_uint2(l0, l1);
    }
}

// ---------------------------------------------------------------------------
// bf16x3 GEMM, pre-split bf16 inputs, 2-stage cp.async double buffer,
// 2 CTAs/SM (<=128 regs). C[m][n] = sum_k A[m][k]*B[n][k], K=768.
// CTA tile 128x128, BK=32, 8 warps (warp tile 64x32). smem row = 80 B.
// ---------------------------------------------------------------------------
#define TILE2 (128 * 80)            // 10240 B per matrix per split per stage
#define STG2  (4 * TILE2)           // 40960 B per stage
#define NSTAGE 2
#define GS2_TOTAL (NSTAGE * STG2)   // 81920 B
#define NKT (DIM / 32)              // 24

template <typename Epi>
__global__ __launch_bounds__(256, 2)
void mgemm2(const __nv_bfloat16* __restrict__ Ah, const __nv_bfloat16* __restrict__ Al,
            const __nv_bfloat16* __restrict__ Bh, const __nv_bfloat16* __restrict__ Bl,
            int M, Epi epi) {
    extern __shared__ char smem[];
    const uint32_t sb = smem_u32(smem);
    const int tid = threadIdx.x;
    const int warp = tid >> 5;
    const int lane = tid & 31;
    const int wm = warp >> 2;
    const int wn = warp & 3;
    const int m0 = blockIdx.y * 128;
    const int n0 = blockIdx.x * 128;

    float acc[4][4][4];
#pragma unroll
    for (int i = 0; i < 4; i++)
#pragma unroll
        for (int j = 0; j < 4; j++)
#pragma unroll
            for (int k = 0; k < 4; k++) acc[i][j][k] = 0.f;

    uint32_t aoff[4], boff[2];
#pragma unroll
    for (int mf = 0; mf < 4; mf++)
        aoff[mf] = (uint32_t)((wm * 64 + mf * 16 + (lane & 15)) * 80 + (lane >> 4) * 16);
#pragma unroll
    for (int pr = 0; pr < 2; pr++)
        boff[pr] = (uint32_t)(2 * TILE2 +
                   (wn * 32 + pr * 16 + ((lane >> 4) * 8) + (lane & 7)) * 80 +
                   ((lane >> 3) & 1) * 16);

    const int r0c = tid >> 2, c40 = tid & 3;
    const int r1c = (tid + 256) >> 2, c41 = (tid + 256) & 3;

    auto load_stage = [&](int kt) {
        const uint32_t sbase = sb + (uint32_t)((kt & (NSTAGE - 1)) * STG2);
#pragma unroll
        for (int i = 0; i < 2; i++) {
            int row = i ? r1c : r0c;
            int c4 = i ? c41 : c40;
            uint32_t doff = (uint32_t)(row * 80 + c4 * 16);
            int m = m0 + row;
            int mc = (m < M) ? m : 0;
            uint32_t sz = (m < M) ? 16u : 0u;
            size_t ga = (size_t)mc * DIM + kt * 32 + c4 * 8;
            cp16(sbase + doff,         Ah + ga, sz);
            cp16(sbase + TILE2 + doff, Al + ga, sz);
            size_t gb = (size_t)(n0 + row) * DIM + kt * 32 + c4 * 8;
            cp16(sbase + 2 * TILE2 + doff, Bh + gb, 16u);
            cp16(sbase + 3 * TILE2 + doff, Bl + gb, 16u);
        }
        CP_COMMIT();
    };

    // low-register compute: B frags resident (16 regs), A frags per-mf (8 regs)
    auto compute = [&](int st) {
        const uint32_t sadd = sb + (uint32_t)(st * STG2);
#pragma unroll
        for (int ks = 0; ks < 2; ks++) {
            uint32_t bh[4][2], bl[4][2];
#pragma unroll
            for (int pr = 0; pr < 2; pr++) {
                uint32_t t[4];
                ldsm4(t, sadd + boff[pr] + ks * 32);
                bh[2 * pr][0] = t[0]; bh[2 * pr][1] = t[1];
                bh[2 * pr + 1][0] = t[2]; bh[2 * pr + 1][1] = t[3];
                ldsm4(t, sadd + TILE2 + boff[pr] + ks * 32);
                bl[2 * pr][0] = t[0]; bl[2 * pr][1] = t[1];
                bl[2 * pr + 1][0] = t[2]; bl[2 * pr + 1][1] = t[3];
            }
#pragma unroll
            for (int mf = 0; mf < 4; mf++) {
                uint32_t ah[4], al[4];
                ldsm4(ah, sadd + aoff[mf] + ks * 32);
                ldsm4(al, sadd + TILE2 + aoff[mf] + ks * 32);
#pragma unroll
                for (int nf = 0; nf < 4; nf++) {
                    mma16816(acc[mf][nf], ah, bh[nf]);
                    mma16816(acc[mf][nf], ah, bl[nf]);
                    mma16816(acc[mf][nf], al, bh[nf]);
                }
            }
        }
    };

    load_stage(0);
    load_stage(1);

    for (int kt = 0; kt < NKT; kt++) {
        CP_WAIT(1);
        __syncthreads();
        compute(kt & 1);
        __syncthreads();
        if (kt + 2 < NKT) load_stage(kt + 2);
    }

    const int g = lane >> 2;
    const int tig = lane & 3;
#pragma unroll
    for (int mf = 0; mf < 4; mf++) {
#pragma unroll
        for (int nf = 0; nf < 4; nf++) {
            int m = m0 + wm * 64 + mf * 16 + g;
            int n = n0 + wn * 32 + nf * 8 + tig * 2;
            if (m < M)     epi(m, n, make_float2(acc[mf][nf][0], acc[mf][nf][1]));
            if (m + 8 < M) epi(m + 8, n, make_float2(acc[mf][nf][2], acc[mf][nf][3]));
        }
    }
}

struct QKVEpiS {
    const float* qb;
    const float* vb;
    __nv_bfloat16 *Qh, *Ql, *Kh, *Kl, *Vh, *Vl;
    __device__ __forceinline__ void operator()(int m, int n, float2 v) const {
        int part = n / DIM;
        int c = n - part * DIM;
        int h = c >> 6;
        int d = c & 63;
        int b = m / NQ;
        int r = m - b * NQ;
        size_t idx = ((size_t)((b * NH + h) * NQ + r)) * HD + d;
        uint32_t hi, lo;
        if (part == 0) {
            v.x = (v.x + qb[c]) * 0.125f;
            v.y = (v.y + qb[c + 1]) * 0.125f;
            split2(v.x, v.y, hi, lo);
            *reinterpret_cast<uint32_t*>(Qh + idx) = hi;
            *reinterpret_cast<uint32_t*>(Ql + idx) = lo;
        } else if (part == 1) {
            split2(v.x, v.y, hi, lo);
            *reinterpret_cast<uint32_t*>(Kh + idx) = hi;
            *reinterpret_cast<uint32_t*>(Kl + idx) = lo;
        } else {
            v.x += vb[c];
            v.y += vb[c + 1];
            split2(v.x, v.y, hi, lo);
            *reinterpret_cast<uint32_t*>(Vh + idx) = hi;
            *reinterpret_cast<uint32_t*>(Vl + idx) = lo;
        }
    }
};

struct ProjEpi2 {
    const float* pb;
    float* out;
    __device__ __forceinline__ void operator()(int m, int n, float2 v) const {
        v.x += pb[n];
        v.y += pb[n + 1];
        *reinterpret_cast<float2*>(out + (size_t)m * DIM + n) = v;
    }
};

// ---------------------------------------------------------------------------
// Tensor-core attention on pre-split bf16 Q/K/V; epilogue writes AO hi/lo.
// ---------------------------------------------------------------------------
#define NQP 208
#define KSTR_B 144
#define AMAT_B (NQP * KSTR_B)
#define ASMEM_TOTAL (6 * AMAT_B + NUM_REL * 4)

__global__ __launch_bounds__(256, 1)
void attn_mma(const __nv_bfloat16* __restrict__ Qh, const __nv_bfloat16* __restrict__ Ql,
              const __nv_bfloat16* __restrict__ Kh, const __nv_bfloat16* __restrict__ Kl,
              const __nv_bfloat16* __restrict__ Vh, const __nv_bfloat16* __restrict__ Vl,
              const float* __restrict__ tabg, const int* __restrict__ ridx,
              __nv_bfloat16* __restrict__ AOh, __nv_bfloat16* __restrict__ AOl) {
    extern __shared__ char sm[];
    const uint32_t sb = smem_u32(sm);
    const uint32_t sQh = sb;
    const uint32_t sQl = sb + AMAT_B;
    const uint32_t sKh = sb + 2 * AMAT_B;
    const uint32_t sKl = sb + 3 * AMAT_B;
    const uint32_t sVh = sb + 4 * AMAT_B;
    const uint32_t sVl = sb + 5 * AMAT_B;
    float* tab = reinterpret_cast<float*>(sm + 6 * AMAT_B);

    const int bh = blockIdx.x;
    const int h = bh % NH;
    const int b = bh / NH;
    const int tid = threadIdx.x;
    const int warp = tid >> 5;
    const int lane = tid & 31;
    const int g = lane >> 2;
    const int tig = lane & 3;
    const size_t base = (size_t)bh * NQ * HD;

    for (int i = tid; i < 11 * 9; i += 256) {
        int r = 197 + i / 9;
        int c = i % 9;
        uint32_t off = (uint32_t)(r * KSTR_B + c * 16);
#pragma unroll
        for (int a = 0; a < 6; a++)
            *reinterpret_cast<uint4*>(sm + a * AMAT_B + off) = make_uint4(0u, 0u, 0u, 0u);
    }
    for (int c = tid; c < NQ * 8; c += 256) {
        int r = c >> 3;
        int col = c & 7;
        uint32_t doff = (uint32_t)(r * KSTR_B + col * 16);
        size_t ga = base + (size_t)r * HD + col * 8;
        cp16(sQh + doff, Qh + ga, 16u);
        cp16(sQl + doff, Ql + ga, 16u);
        cp16(sKh + doff, Kh + ga, 16u);
        cp16(sKl + doff, Kl + ga, 16u);
        cp16(sVh + doff, Vh + ga, 16u);
        cp16(sVl + doff, Vl + ga, 16u);
    }
    CP_COMMIT();
    for (int i = tid; i < NUM_REL; i += 256) tab[i] = tabg[i * NH + h];
    CP_WAIT(0);
    __syncthreads();

    for (int blk = warp; blk < 13; blk += 8) {
        float s[26][4];
#pragma unroll
        for (int nc = 0; nc < 26; nc++)
#pragma unroll
            for (int e = 0; e < 4; e++) s[nc][e] = 0.f;

        const uint32_t qrow = (uint32_t)((blk * 16 + (lane & 15)) * KSTR_B + (lane >> 4) * 16);
        const uint32_t krow = (uint32_t)(((lane >> 4) * 8 + (lane & 7)) * KSTR_B + ((lane >> 3) & 1) * 16);

#pragma unroll
        for (int kc = 0; kc < 4; kc++) {
            uint32_t qh[4], ql[4];
            ldsm4(qh, sQh + qrow + kc * 32);
            ldsm4(ql, sQl + qrow + kc * 32);
#pragma unroll
            for (int np = 0; np < 13; np++) {
                uint32_t th[4], tl[4];
                ldsm4(th, sKh + krow + (uint32_t)(np * 16 * KSTR_B) + kc * 32);
                ldsm4(tl, sKl + krow + (uint32_t)(np * 16 * KSTR_B) + kc * 32);
                mma16816(s[2 * np],     qh, th);
                mma16816(s[2 * np],     qh, tl);
                mma16816(s[2 * np],     ql, th);
                mma16816(s[2 * np + 1], qh, th + 2);
                mma16816(s[2 * np + 1], qh, tl + 2);
                mma16816(s[2 * np + 1], ql, th + 2);
            }
        }

        const int q0 = blk * 16 + g;
        const int q1 = q0 + 8;
        const int* r0 = ridx + (size_t)min(q0, NQ - 1) * NQ;
        const int* r1 = ridx + (size_t)min(q1, NQ - 1) * NQ;
#pragma unroll
        for (int nc = 0; nc < 26; nc++) {
            int n0 = nc * 8 + tig * 2;
            if (n0 < NQ) { s[nc][0] += tab[r0[n0]]; s[nc][2] += tab[r1[n0]]; }
            else         { s[nc][0] = -1e30f;       s[nc][2] = -1e30f; }
            int n1 = n0 + 1;
            if (n1 < NQ) { s[nc][1] += tab[r0[n1]]; s[nc][3] += tab[r1[n1]]; }
            else         { s[nc][1] = -1e30f;       s[nc][3] = -1e30f; }
        }

        float mx0 = -1e30f, mx1 = -1e30f;
#pragma unroll
        for (int nc = 0; nc < 26; nc++) {
            mx0 = fmaxf(mx0, fmaxf(s[nc][0], s[nc][1]));
            mx1 = fmaxf(mx1, fmaxf(s[nc][2], s[nc][3]));
        }
        mx0 = fmaxf(mx0, __shfl_xor_sync(0xffffffffu, mx0, 1));
        mx0 = fmaxf(mx0, __shfl_xor_sync(0xffffffffu, mx0, 2));
        mx1 = fmaxf(mx1, __shfl_xor_sync(0xffffffffu, mx1, 1));
        mx1 = fmaxf(mx1, __shfl_xor_sync(0xffffffffu, mx1, 2));

        float sum0 = 0.f, sum1 = 0.f;
#pragma unroll
        for (int nc = 0; nc < 26; nc++) {
            s[nc][0] = __expf(s[nc][0] - mx0);
            s[nc][1] = __expf(s[nc][1] - mx0);
            s[nc][2] = __expf(s[nc][2] - mx1);
            s[nc][3] = __expf(s[nc][3] - mx1);
            sum0 += s[nc][0] + s[nc][1];
            sum1 += s[nc][2] + s[nc][3];
        }
        sum0 += __shfl_xor_sync(0xffffffffu, sum0, 1);
        sum0 += __shfl_xor_sync(0xffffffffu, sum0, 2);
        sum1 += __shfl_xor_sync(0xffffffffu, sum1, 1);
        sum1 += __shfl_xor_sync(0xffffffffu, sum1, 2);
        float inv0 = __frcp_rn(sum0);
        float inv1 = __frcp_rn(sum1);
#pragma unroll
        for (int nc = 0; nc < 26; nc++) {
            s[nc][0] *= inv0; s[nc][1] *= inv0;
            s[nc][2] *= inv1; s[nc][3] *= inv1;
        }

        float o[8][4];
#pragma unroll
        for (int nd = 0; nd < 8; nd++)
#pragma unroll
            for (int e = 0; e < 4; e++) o[nd][e] = 0.f;

        const uint32_t vrow = (uint32_t)((((lane >> 3) & 1) * 8 + (lane & 7)) * KSTR_B + (lane >> 4) * 16);

#pragma unroll
        for (int kc = 0; kc < 13; kc++) {
            uint32_t ph[4], pl[4];
            split2(s[2 * kc][0],     s[2 * kc][1],     ph[0], pl[0]);
            split2(s[2 * kc][2],     s[2 * kc][3],     ph[1], pl[1]);
            split2(s[2 * kc + 1][0], s[2 * kc + 1][1], ph[2], pl[2]);
            split2(s[2 * kc + 1][2], s[2 * kc + 1][3], ph[3], pl[3]);
#pragma unroll
            for (int dg = 0; dg < 4; dg++) {
                uint32_t bh4[4], bl4[4];
                ldsm4t(bh4, sVh + vrow + (uint32_t)(kc * 16 * KSTR_B) + dg * 32);
                ldsm4t(bl4, sVl + vrow + (uint32_t)(kc * 16 * KSTR_B) + dg * 32);
                mma16816(o[2 * dg],     ph, bh4);
                mma16816(o[2 * dg],     ph, bl4);
                mma16816(o[2 * dg],     pl, bh4);
                mma16816(o[2 * dg + 1], ph, bh4 + 2);
                mma16816(o[2 * dg + 1], ph, bl4 + 2);
                mma16816(o[2 * dg + 1], pl, bh4 + 2);
            }
        }

        if (q0 < NQ) {
            size_t ob = ((size_t)(b * NQ + q0) * NH + h) * HD + tig * 2;
#pragma unroll
            for (int nd = 0; nd < 8; nd++) {
                uint32_t hi, lo;
                split2(o[nd][0], o[nd][1], hi, lo);
                *reinterpret_cast<uint32_t*>(AOh + ob + nd * 8) = hi;
                *reinterpret_cast<uint32_t*>(AOl + ob + nd * 8) = lo;
            }
        }
        if (q1 < NQ) {
            size_t ob = ((size_t)(b * NQ + q1) * NH + h) * HD + tig * 2;
#pragma unroll
            for (int nd = 0; nd < 8; nd++) {
                uint32_t hi, lo;
                split2(o[nd][2], o[nd][3], hi, lo);
                *reinterpret_cast<uint32_t*>(AOh + ob + nd * 8) = hi;
                *reinterpret_cast<uint32_t*>(AOl + ob + nd * 8) = lo;
            }
        }
    }
}

// ---------------------------------------------------------------------------
extern "C" void kernel_launch(void* const* d_in, const int* in_sizes, int n_in,
                              void* d_out, int out_size) {
    const float* x      = (const float*)d_in[0];
    const float* qkv_w  = (const float*)d_in[1];
    const float* q_bias = (const float*)d_in[2];
    const float* v_bias = (const float*)d_in[3];
    const float* rpb    = (const float*)d_in[4];
    const float* proj_w = (const float*)d_in[5];
    const float* proj_b = (const float*)d_in[6];
    const int*   ridx   = (const int*)d_in[7];
    float* out = (float*)d_out;

    __nv_bfloat16 *Xh, *Xl, *W1h, *W1l, *W2h, *W2l;
    __nv_bfloat16 *Qh, *Ql, *Kh, *Kl, *Vh, *Vl, *AOh, *AOl;
    cudaGetSymbolAddress((void**)&Xh, g_Xh);   cudaGetSymbolAddress((void**)&Xl, g_Xl);
    cudaGetSymbolAddress((void**)&W1h, g_W1h); cudaGetSymbolAddress((void**)&W1l, g_W1l);
    cudaGetSymbolAddress((void**)&W2h, g_W2h); cudaGetSymbolAddress((void**)&W2l, g_W2l);
    cudaGetSymbolAddress((void**)&Qh, g_Qh);   cudaGetSymbolAddress((void**)&Ql, g_Ql);
    cudaGetSymbolAddress((void**)&Kh, g_Kh);   cudaGetSymbolAddress((void**)&Kl, g_Kl);
    cudaGetSymbolAddress((void**)&Vh, g_Vh);   cudaGetSymbolAddress((void**)&Vl, g_Vl);
    cudaGetSymbolAddress((void**)&AOh, g_AOh); cudaGetSymbolAddress((void**)&AOl, g_AOl);

    cudaFuncSetAttribute(mgemm2<QKVEpiS>, cudaFuncAttributeMaxDynamicSharedMemorySize, GS2_TOTAL);
    cudaFuncSetAttribute(mgemm2<ProjEpi2>, cudaFuncAttributeMaxDynamicSharedMemorySize, GS2_TOTAL);
    cudaFuncSetAttribute(attn_mma, cudaFuncAttributeMaxDynamicSharedMemorySize, ASMEM_TOTAL);

    // 0) precompute bf16 hi/lo splits
    split_kernel<<<(XN / 4 + 255) / 256, 256>>>(x, Xh, Xl, XN / 4);
    split_kernel<<<(W1N / 4 + 255) / 256, 256>>>(qkv_w, W1h, W1l, W1N / 4);
    split_kernel<<<(W2N / 4 + 255) / 256, 256>>>(proj_w, W2h, W2l, W2N / 4);

    // 1) fused QKV projection -> pre-split Q (scaled), K, V
    QKVEpiS e1{q_bias, v_bias, Qh, Ql, Kh, Kl, Vh, Vl};
    mgemm2<QKVEpiS><<<dim3(3 * DIM / 128, (MROWS + 127) / 128), 256, GS2_TOTAL>>>(
        Xh, Xl, W1h, W1l, MROWS, e1);

    // 2) tensor-core attention with relative position bias
    attn_mma<<<BATCH * NH, 256, ASMEM_TOTAL>>>(Qh, Ql, Kh, Kl, Vh, Vl, rpb, ridx, AOh, AOl);

    // 3) output projection
    ProjEpi2 e2{proj_b, out};
    mgemm2<ProjEpi2><<<dim3(DIM / 128, (MROWS + 127) / 128), 256, GS2_TOTAL>>>(
        AOh, AOl, W2h, W2l, MROWS, e2);
}

// round 7
// speedup vs baseline: 1.1468x; 1.0038x over previous
#include <cuda_runtime.h>
#include <cuda_bf16.h>
#include <cstdint>

#define BATCH 64
#define NQ 197
#define DIM 768
#define NH 12
#define HD 64
#define NUM_REL 732
#define MROWS (BATCH * NQ)   // 12608

#define XN (MROWS * DIM)
#define QKN (BATCH * NH * NQ * HD)
#define W1N (3 * DIM * DIM)
#define W2N (DIM * DIM)

static __device__ __nv_bfloat16 g_Xh[XN],  g_Xl[XN];
static __device__ __nv_bfloat16 g_W1h[W1N], g_W1l[W1N];
static __device__ __nv_bfloat16 g_W2h[W2N], g_W2l[W2N];
static __device__ __nv_bfloat16 g_Qh[QKN], g_Ql[QKN];
static __device__ __nv_bfloat16 g_Kh[QKN], g_Kl[QKN];
static __device__ __nv_bfloat16 g_Vh[QKN], g_Vl[QKN];
static __device__ __nv_bfloat16 g_AOh[XN], g_AOl[XN];

// ---------------------------------------------------------------------------
// helpers
// ---------------------------------------------------------------------------
__device__ __forceinline__ uint32_t smem_u32(const void* p) {
    uint32_t a;
    asm("{ .reg .u64 t; cvta.to.shared.u64 t, %1; cvt.u32.u64 %0, t; }" : "=r"(a) : "l"(p));
    return a;
}

__device__ __forceinline__ void ldsm4(uint32_t* r, uint32_t addr) {
    asm volatile("ldmatrix.sync.aligned.m8n8.x4.shared.b16 {%0,%1,%2,%3}, [%4];"
                 : "=r"(r[0]), "=r"(r[1]), "=r"(r[2]), "=r"(r[3]) : "r"(addr));
}

__device__ __forceinline__ void ldsm4t(uint32_t* r, uint32_t addr) {
    asm volatile("ldmatrix.sync.aligned.m8n8.x4.trans.shared.b16 {%0,%1,%2,%3}, [%4];"
                 : "=r"(r[0]), "=r"(r[1]), "=r"(r[2]), "=r"(r[3]) : "r"(addr));
}

__device__ __forceinline__ void mma16816(float* c, const uint32_t* a, const uint32_t* b) {
    asm volatile(
        "mma.sync.aligned.m16n8k16.row.col.f32.bf16.bf16.f32 "
        "{%0,%1,%2,%3}, {%4,%5,%6,%7}, {%8,%9}, {%0,%1,%2,%3};"
        : "+f"(c[0]), "+f"(c[1]), "+f"(c[2]), "+f"(c[3])
        : "r"(a[0]), "r"(a[1]), "r"(a[2]), "r"(a[3]), "r"(b[0]), "r"(b[1]));
}

__device__ __forceinline__ void split2(float x, float y, uint32_t& hi, uint32_t& lo) {
    __nv_bfloat162 h = __floats2bfloat162_rn(x, y);
    float hx = __bfloat162float(h.x);
    float hy = __bfloat162float(h.y);
    __nv_bfloat162 l = __floats2bfloat162_rn(x - hx, y - hy);
    hi = *reinterpret_cast<uint32_t*>(&h);
    lo = *reinterpret_cast<uint32_t*>(&l);
}

__device__ __forceinline__ void cp16(uint32_t dst, const void* src, uint32_t srcbytes) {
    asm volatile("cp.async.cg.shared.global [%0], [%1], 16, %2;"
                 :: "r"(dst), "l"(src), "r"(srcbytes) : "memory");
}
#define CP_COMMIT() asm volatile("cp.async.commit_group;" ::: "memory")
#define CP_WAIT(N)  asm volatile("cp.async.wait_group %0;" :: "n"(N) : "memory")

// ---------------------------------------------------------------------------
// split kernel: fp32 -> bf16 hi/lo
// ---------------------------------------------------------------------------
__global__ void split_kernel(const float* __restrict__ in, __nv_bfloat16* __restrict__ hi,
                             __nv_bfloat16* __restrict__ lo, int n4) {
    int i = blockIdx.x * 256 + threadIdx.x;
    if (i < n4) {
        float4 v = reinterpret_cast<const float4*>(in)[i];
        uint32_t h0, l0, h1, l1;
        split2(v.x, v.y, h0, l0);
        split2(v.z, v.w, h1, l1);
        reinterpret_cast<uint2*>(hi)[i] = make_uint2(h0, h1);
        reinterpret_cast<uint2*>(lo)[i] = make_uint2(l0, l1);
    }
}

// ---------------------------------------------------------------------------
// bf16x3 GEMM, pre-split bf16 inputs, 2-stage cp.async double buffer,
// 2 CTAs/SM. Inner MMAs term-major -> dependent-chain distance 4.
// ---------------------------------------------------------------------------
#define TILE2 (128 * 80)
#define STG2  (4 * TILE2)
#define NSTAGE 2
#define GS2_TOTAL (NSTAGE * STG2)
#define NKT (DIM / 32)

template <typename Epi>
__global__ __launch_bounds__(256, 2)
void mgemm2(const __nv_bfloat16* __restrict__ Ah, const __nv_bfloat16* __restrict__ Al,
            const __nv_bfloat16* __restrict__ Bh, const __nv_bfloat16* __restrict__ Bl,
            int M, Epi epi) {
    extern __shared__ char smem[];
    const uint32_t sb = smem_u32(smem);
    const int tid = threadIdx.x;
    const int warp = tid >> 5;
    const int lane = tid & 31;
    const int wm = warp >> 2;
    const int wn = warp & 3;
    const int m0 = blockIdx.y * 128;
    const int n0 = blockIdx.x * 128;

    float acc[4][4][4];
#pragma unroll
    for (int i = 0; i < 4; i++)
#pragma unroll
        for (int j = 0; j < 4; j++)
#pragma unroll
            for (int k = 0; k < 4; k++) acc[i][j][k] = 0.f;

    uint32_t aoff[4], boff[2];
#pragma unroll
    for (int mf = 0; mf < 4; mf++)
        aoff[mf] = (uint32_t)((wm * 64 + mf * 16 + (lane & 15)) * 80 + (lane >> 4) * 16);
#pragma unroll
    for (int pr = 0; pr < 2; pr++)
        boff[pr] = (uint32_t)(2 * TILE2 +
                   (wn * 32 + pr * 16 + ((lane >> 4) * 8) + (lane & 7)) * 80 +
                   ((lane >> 3) & 1) * 16);

    const int r0c = tid >> 2, c40 = tid & 3;
    const int r1c = (tid + 256) >> 2, c41 = (tid + 256) & 3;

    auto load_stage = [&](int kt) {
        const uint32_t sbase = sb + (uint32_t)((kt & (NSTAGE - 1)) * STG2);
#pragma unroll
        for (int i = 0; i < 2; i++) {
            int row = i ? r1c : r0c;
            int c4 = i ? c41 : c40;
            uint32_t doff = (uint32_t)(row * 80 + c4 * 16);
            int m = m0 + row;
            int mc = (m < M) ? m : 0;
            uint32_t sz = (m < M) ? 16u : 0u;
            size_t ga = (size_t)mc * DIM + kt * 32 + c4 * 8;
            cp16(sbase + doff,         Ah + ga, sz);
            cp16(sbase + TILE2 + doff, Al + ga, sz);
            size_t gb = (size_t)(n0 + row) * DIM + kt * 32 + c4 * 8;
            cp16(sbase + 2 * TILE2 + doff, Bh + gb, 16u);
            cp16(sbase + 3 * TILE2 + doff, Bl + gb, 16u);
        }
        CP_COMMIT();
    };

    auto compute = [&](int st) {
        const uint32_t sadd = sb + (uint32_t)(st * STG2);
#pragma unroll
        for (int ks = 0; ks < 2; ks++) {
            uint32_t bh[4][2], bl[4][2];
#pragma unroll
            for (int pr = 0; pr < 2; pr++) {
                uint32_t t[4];
                ldsm4(t, sadd + boff[pr] + ks * 32);
                bh[2 * pr][0] = t[0]; bh[2 * pr][1] = t[1];
                bh[2 * pr + 1][0] = t[2]; bh[2 * pr + 1][1] = t[3];
                ldsm4(t, sadd + TILE2 + boff[pr] + ks * 32);
                bl[2 * pr][0] = t[0]; bl[2 * pr][1] = t[1];
                bl[2 * pr + 1][0] = t[2]; bl[2 * pr + 1][1] = t[3];
            }
#pragma unroll
            for (int mf = 0; mf < 4; mf++) {
                uint32_t ah[4], al[4];
                ldsm4(ah, sadd + aoff[mf] + ks * 32);
                ldsm4(al, sadd + TILE2 + aoff[mf] + ks * 32);
                // term-major: dependent updates to acc[mf][nf] are 4 apart
#pragma unroll
                for (int nf = 0; nf < 4; nf++) mma16816(acc[mf][nf], ah, bh[nf]);
#pragma unroll
                for (int nf = 0; nf < 4; nf++) mma16816(acc[mf][nf], ah, bl[nf]);
#pragma unroll
                for (int nf = 0; nf < 4; nf++) mma16816(acc[mf][nf], al, bh[nf]);
            }
        }
    };

    load_stage(0);
    load_stage(1);

    for (int kt = 0; kt < NKT; kt++) {
        CP_WAIT(1);
        __syncthreads();
        compute(kt & 1);
        __syncthreads();
        if (kt + 2 < NKT) load_stage(kt + 2);
    }

    const int g = lane >> 2;
    const int tig = lane & 3;
#pragma unroll
    for (int mf = 0; mf < 4; mf++) {
#pragma unroll
        for (int nf = 0; nf < 4; nf++) {
            int m = m0 + wm * 64 + mf * 16 + g;
            int n = n0 + wn * 32 + nf * 8 + tig * 2;
            if (m < M)     epi(m, n, make_float2(acc[mf][nf][0], acc[mf][nf][1]));
            if (m + 8 < M) epi(m + 8, n, make_float2(acc[mf][nf][2], acc[mf][nf][3]));
        }
    }
}

struct QKVEpiS {
    const float* qb;
    const float* vb;
    __nv_bfloat16 *Qh, *Ql, *Kh, *Kl, *Vh, *Vl;
    __device__ __forceinline__ void operator()(int m, int n, float2 v) const {
        int part = n / DIM;
        int c = n - part * DIM;
        int h = c >> 6;
        int d = c & 63;
        int b = m / NQ;
        int r = m - b * NQ;
        size_t idx = ((size_t)((b * NH + h) * NQ + r)) * HD + d;
        uint32_t hi, lo;
        if (part == 0) {
            v.x = (v.x + qb[c]) * 0.125f;
            v.y = (v.y + qb[c + 1]) * 0.125f;
            split2(v.x, v.y, hi, lo);
            *reinterpret_cast<uint32_t*>(Qh + idx) = hi;
            *reinterpret_cast<uint32_t*>(Ql + idx) = lo;
        } else if (part == 1) {
            split2(v.x, v.y, hi, lo);
            *reinterpret_cast<uint32_t*>(Kh + idx) = hi;
            *reinterpret_cast<uint32_t*>(Kl + idx) = lo;
        } else {
            v.x += vb[c];
            v.y += vb[c + 1];
            split2(v.x, v.y, hi, lo);
            *reinterpret_cast<uint32_t*>(Vh + idx) = hi;
            *reinterpret_cast<uint32_t*>(Vl + idx) = lo;
        }
    }
};

struct ProjEpi2 {
    const float* pb;
    float* out;
    __device__ __forceinline__ void operator()(int m, int n, float2 v) const {
        v.x += pb[n];
        v.y += pb[n + 1];
        *reinterpret_cast<float2*>(out + (size_t)m * DIM + n) = v;
    }
};

// ---------------------------------------------------------------------------
// Tensor-core attention; MMA chains interleaved across paired accumulators.
// ---------------------------------------------------------------------------
#define NQP 208
#define KSTR_B 144
#define AMAT_B (NQP * KSTR_B)
#define ASMEM_TOTAL (6 * AMAT_B + NUM_REL * 4)

__global__ __launch_bounds__(256, 1)
void attn_mma(const __nv_bfloat16* __restrict__ Qh, const __nv_bfloat16* __restrict__ Ql,
              const __nv_bfloat16* __restrict__ Kh, const __nv_bfloat16* __restrict__ Kl,
              const __nv_bfloat16* __restrict__ Vh, const __nv_bfloat16* __restrict__ Vl,
              const float* __restrict__ tabg, const int* __restrict__ ridx,
              __nv_bfloat16* __restrict__ AOh, __nv_bfloat16* __restrict__ AOl) {
    extern __shared__ char sm[];
    const uint32_t sb = smem_u32(sm);
    const uint32_t sQh = sb;
    const uint32_t sQl = sb + AMAT_B;
    const uint32_t sKh = sb + 2 * AMAT_B;
    const uint32_t sKl = sb + 3 * AMAT_B;
    const uint32_t sVh = sb + 4 * AMAT_B;
    const uint32_t sVl = sb + 5 * AMAT_B;
    float* tab = reinterpret_cast<float*>(sm + 6 * AMAT_B);

    const int bh = blockIdx.x;
    const int h = bh % NH;
    const int b = bh / NH;
    const int tid = threadIdx.x;
    const int warp = tid >> 5;
    const int lane = tid & 31;
    const int g = lane >> 2;
    const int tig = lane & 3;
    const size_t base = (size_t)bh * NQ * HD;

    for (int i = tid; i < 11 * 9; i += 256) {
        int r = 197 + i / 9;
        int c = i % 9;
        uint32_t off = (uint32_t)(r * KSTR_B + c * 16);
#pragma unroll
        for (int a = 0; a < 6; a++)
            *reinterpret_cast<uint4*>(sm + a * AMAT_B + off) = make_uint4(0u, 0u, 0u, 0u);
    }
    for (int c = tid; c < NQ * 8; c += 256) {
        int r = c >> 3;
        int col = c & 7;
        uint32_t doff = (uint32_t)(r * KSTR_B + col * 16);
        size_t ga = base + (size_t)r * HD + col * 8;
        cp16(sQh + doff, Qh + ga, 16u);
        cp16(sQl + doff, Ql + ga, 16u);
        cp16(sKh + doff, Kh + ga, 16u);
        cp16(sKl + doff, Kl + ga, 16u);
        cp16(sVh + doff, Vh + ga, 16u);
        cp16(sVl + doff, Vl + ga, 16u);
    }
    CP_COMMIT();
    for (int i = tid; i < NUM_REL; i += 256) tab[i] = tabg[i * NH + h];
    CP_WAIT(0);
    __syncthreads();

    for (int blk = warp; blk < 13; blk += 8) {
        float s[26][4];
#pragma unroll
        for (int nc = 0; nc < 26; nc++)
#pragma unroll
            for (int e = 0; e < 4; e++) s[nc][e] = 0.f;

        const uint32_t qrow = (uint32_t)((blk * 16 + (lane & 15)) * KSTR_B + (lane >> 4) * 16);
        const uint32_t krow = (uint32_t)(((lane >> 4) * 8 + (lane & 7)) * KSTR_B + ((lane >> 3) & 1) * 16);

#pragma unroll
        for (int kc = 0; kc < 4; kc++) {
            uint32_t qh[4], ql[4];
            ldsm4(qh, sQh + qrow + kc * 32);
            ldsm4(ql, sQl + qrow + kc * 32);
#pragma unroll
            for (int np = 0; np < 13; np++) {
                uint32_t th[4], tl[4];
                ldsm4(th, sKh + krow + (uint32_t)(np * 16 * KSTR_B) + kc * 32);
                ldsm4(tl, sKl + krow + (uint32_t)(np * 16 * KSTR_B) + kc * 32);
                // interleave the two accumulators: chain distance 2
                mma16816(s[2 * np],     qh, th);
                mma16816(s[2 * np + 1], qh, th + 2);
                mma16816(s[2 * np],     qh, tl);
                mma16816(s[2 * np + 1], qh, tl + 2);
                mma16816(s[2 * np],     ql, th);
                mma16816(s[2 * np + 1], ql, th + 2);
            }
        }

        const int q0 = blk * 16 + g;
        const int q1 = q0 + 8;
        const int* r0 = ridx + (size_t)min(q0, NQ - 1) * NQ;
        const int* r1 = ridx + (size_t)min(q1, NQ - 1) * NQ;
#pragma unroll
        for (int nc = 0; nc < 26; nc++) {
            int n0 = nc * 8 + tig * 2;
            if (n0 < NQ) { s[nc][0] += tab[r0[n0]]; s[nc][2] += tab[r1[n0]]; }
            else         { s[nc][0] = -1e30f;       s[nc][2] = -1e30f; }
            int n1 = n0 + 1;
            if (n1 < NQ) { s[nc][1] += tab[r0[n1]]; s[nc][3] += tab[r1[n1]]; }
            else         { s[nc][1] = -1e30f;       s[nc][3] = -1e30f; }
        }

        float mx0 = -1e30f, mx1 = -1e30f;
#pragma unroll
        for (int nc = 0; nc < 26; nc++) {
            mx0 = fmaxf(mx0, fmaxf(s[nc][0], s[nc][1]));
            mx1 = fmaxf(mx1, fmaxf(s[nc][2], s[nc][3]));
        }
        mx0 = fmaxf(mx0, __shfl_xor_sync(0xffffffffu, mx0, 1));
        mx0 = fmaxf(mx0, __shfl_xor_sync(0xffffffffu, mx0, 2));
        mx1 = fmaxf(mx1, __shfl_xor_sync(0xffffffffu, mx1, 1));
        mx1 = fmaxf(mx1, __shfl_xor_sync(0xffffffffu, mx1, 2));

        float sum0 = 0.f, sum1 = 0.f;
#pragma unroll
        for (int nc = 0; nc < 26; nc++) {
            s[nc][0] = __expf(s[nc][0] - mx0);
            s[nc][1] = __expf(s[nc][1] - mx0);
            s[nc][2] = __expf(s[nc][2] - mx1);
            s[nc][3] = __expf(s[nc][3] - mx1);
            sum0 += s[nc][0] + s[nc][1];
            sum1 += s[nc][2] + s[nc][3];
        }
        sum0 += __shfl_xor_sync(0xffffffffu, sum0, 1);
        sum0 += __shfl_xor_sync(0xffffffffu, sum0, 2);
        sum1 += __shfl_xor_sync(0xffffffffu, sum1, 1);
        sum1 += __shfl_xor_sync(0xffffffffu, sum1, 2);
        float inv0 = __frcp_rn(sum0);
        float inv1 = __frcp_rn(sum1);
#pragma unroll
        for (int nc = 0; nc < 26; nc++) {
            s[nc][0] *= inv0; s[nc][1] *= inv0;
            s[nc][2] *= inv1; s[nc][3] *= inv1;
        }

        float o[8][4];
#pragma unroll
        for (int nd = 0; nd < 8; nd++)
#pragma unroll
            for (int e = 0; e < 4; e++) o[nd][e] = 0.f;

        const uint32_t vrow = (uint32_t)((((lane >> 3) & 1) * 8 + (lane & 7)) * KSTR_B + (lane >> 4) * 16);

#pragma unroll
        for (int kc = 0; kc < 13; kc++) {
            uint32_t ph[4], pl[4];
            split2(s[2 * kc][0],     s[2 * kc][1],     ph[0], pl[0]);
            split2(s[2 * kc][2],     s[2 * kc][3],     ph[1], pl[1]);
            split2(s[2 * kc + 1][0], s[2 * kc + 1][1], ph[2], pl[2]);
            split2(s[2 * kc + 1][2], s[2 * kc + 1][3], ph[3], pl[3]);
#pragma unroll
            for (int dg = 0; dg < 4; dg++) {
                uint32_t bh4[4], bl4[4];
                ldsm4t(bh4, sVh + vrow + (uint32_t)(kc * 16 * KSTR_B) + dg * 32);
                ldsm4t(bl4, sVl + vrow + (uint32_t)(kc * 16 * KSTR_B) + dg * 32);
                // interleave paired accumulators: chain distance 2
                mma16816(o[2 * dg],     ph, bh4);
                mma16816(o[2 * dg + 1], ph, bh4 + 2);
                mma16816(o[2 * dg],     ph, bl4);
                mma16816(o[2 * dg + 1], ph, bl4 + 2);
                mma16816(o[2 * dg],     pl, bh4);
                mma16816(o[2 * dg + 1], pl, bh4 + 2);
            }
        }

        if (q0 < NQ) {
            size_t ob = ((size_t)(b * NQ + q0) * NH + h) * HD + tig * 2;
#pragma unroll
            for (int nd = 0; nd < 8; nd++) {
                uint32_t hi, lo;
                split2(o[nd][0], o[nd][1], hi, lo);
                *reinterpret_cast<uint32_t*>(AOh + ob + nd * 8) = hi;
                *reinterpret_cast<uint32_t*>(AOl + ob + nd * 8) = lo;
            }
        }
        if (q1 < NQ) {
            size_t ob = ((size_t)(b * NQ + q1) * NH + h) * HD + tig * 2;
#pragma unroll
            for (int nd = 0; nd < 8; nd++) {
                uint32_t hi, lo;
                split2(o[nd][2], o[nd][3], hi, lo);
                *reinterpret_cast<uint32_t*>(AOh + ob + nd * 8) = hi;
                *reinterpret_cast<uint32_t*>(AOl + ob + nd * 8) = lo;
            }
        }
    }
}

// ---------------------------------------------------------------------------
extern "C" void kernel_launch(void* const* d_in, const int* in_sizes, int n_in,
                              void* d_out, int out_size) {
    const float* x      = (const float*)d_in[0];
    const float* qkv_w  = (const float*)d_in[1];
    const float* q_bias = (const float*)d_in[2];
    const float* v_bias = (const float*)d_in[3];
    const float* rpb    = (const float*)d_in[4];
    const float* proj_w = (const float*)d_in[5];
    const float* proj_b = (const float*)d_in[6];
    const int*   ridx   = (const int*)d_in[7];
    float* out = (float*)d_out;

    __nv_bfloat16 *Xh, *Xl, *W1h, *W1l, *W2h, *W2l;
    __nv_bfloat16 *Qh, *Ql, *Kh, *Kl, *Vh, *Vl, *AOh, *AOl;
    cudaGetSymbolAddress((void**)&Xh, g_Xh);   cudaGetSymbolAddress((void**)&Xl, g_Xl);
    cudaGetSymbolAddress((void**)&W1h, g_W1h); cudaGetSymbolAddress((void**)&W1l, g_W1l);
    cudaGetSymbolAddress((void**)&W2h, g_W2h); cudaGetSymbolAddress((void**)&W2l, g_W2l);
    cudaGetSymbolAddress((void**)&Qh, g_Qh);   cudaGetSymbolAddress((void**)&Ql, g_Ql);
    cudaGetSymbolAddress((void**)&Kh, g_Kh);   cudaGetSymbolAddress((void**)&Kl, g_Kl);
    cudaGetSymbolAddress((void**)&Vh, g_Vh);   cudaGetSymbolAddress((void**)&Vl, g_Vl);
    cudaGetSymbolAddress((void**)&AOh, g_AOh); cudaGetSymbolAddress((void**)&AOl, g_AOl);

    cudaFuncSetAttribute(mgemm2<QKVEpiS>, cudaFuncAttributeMaxDynamicSharedMemorySize, GS2_TOTAL);
    cudaFuncSetAttribute(mgemm2<ProjEpi2>, cudaFuncAttributeMaxDynamicSharedMemorySize, GS2_TOTAL);
    cudaFuncSetAttribute(attn_mma, cudaFuncAttributeMaxDynamicSharedMemorySize, ASMEM_TOTAL);

    // 0) precompute bf16 hi/lo splits
    split_kernel<<<(XN / 4 + 255) / 256, 256>>>(x, Xh, Xl, XN / 4);
    split_kernel<<<(W1N / 4 + 255) / 256, 256>>>(qkv_w, W1h, W1l, W1N / 4);
    split_kernel<<<(W2N / 4 + 255) / 256, 256>>>(proj_w, W2h, W2l, W2N / 4);

    // 1) fused QKV projection -> pre-split Q (scaled), K, V
    QKVEpiS e1{q_bias, v_bias, Qh, Ql, Kh, Kl, Vh, Vl};
    mgemm2<QKVEpiS><<<dim3(3 * DIM / 128, (MROWS + 127) / 128), 256, GS2_TOTAL>>>(
        Xh, Xl, W1h, W1l, MROWS, e1);

    // 2) tensor-core attention with relative position bias
    attn_mma<<<BATCH * NH, 256, ASMEM_TOTAL>>>(Qh, Ql, Kh, Kl, Vh, Vl, rpb, ridx, AOh, AOl);

    // 3) output projection
    ProjEpi2 e2{proj_b, out};
    mgemm2<ProjEpi2><<<dim3(DIM / 128, (MROWS + 127) / 128), 256, GS2_TOTAL>>>(
        AOh, AOl, W2h, W2l, MROWS, e2);
}